// round 2
// baseline (speedup 1.0000x reference)
#include <cuda_runtime.h>

#define NN 50000
#define NE 800000
#define IND 128
#define HID 64
#define HEADS 4
#define C1 256            // HEADS*HID
#define EDIM 16
#define ENC_NEG_INF 0x007FFFFFu

// ---------------- scratch (device globals; no allocation allowed) ----------
__device__ float4  g_h1[NN * C1 / 4];       // [N,256] layer-1 transformed feats
__device__ float4  g_out1[NN * C1 / 4];     // layer-1 aggregation accumulator
__device__ float4  g_h2[NN * HID / 4];      // [N,64] layer-2 transformed feats
__device__ float4  g_out2[NN * HID / 4];    // layer-2 aggregation accumulator
__device__ float4  g_scr1[NE];              // per-edge logits -> exp (4 heads)
__device__ float   g_scr2[NE];              // per-edge logits -> exp (1 head)
__device__ float   g_ae2[NE];               // layer-2 edge-attr attention term
__device__ float4  g_asrc1[NN], g_adst1[NN];
__device__ float   g_asrc2[NN], g_adst2[NN];
__device__ unsigned g_amax1[NN * 4];
__device__ float4  g_den1[NN];
__device__ unsigned g_amax2[NN];
__device__ float   g_den2[NN];
__device__ float   g_v1[EDIM * HEADS];      // (We1 . ae1) collapsed: v1[d*4+h]
__device__ float   g_v2[EDIM];

// ---------------- helpers ----------------
__device__ __forceinline__ unsigned f2o(float f) {
    unsigned u = __float_as_uint(f);
    return (u & 0x80000000u) ? ~u : (u | 0x80000000u);
}
__device__ __forceinline__ float o2f(unsigned u) {
    return (u & 0x80000000u) ? __uint_as_float(u & 0x7FFFFFFFu)
                             : __uint_as_float(~u);
}
__device__ __forceinline__ void red_add_v4(float* a, float4 v) {
    asm volatile("red.global.add.v4.f32 [%0], {%1,%2,%3,%4};"
                 :: "l"(a), "f"(v.x), "f"(v.y), "f"(v.z), "f"(v.w) : "memory");
}
__device__ __forceinline__ float lrelu(float x) { return x > 0.f ? x : 0.2f * x; }

// ---------------- kernels ----------------
__global__ __launch_bounds__(256) void k_init() {
    int i = blockIdx.x * blockDim.x + threadIdx.x;
    float4 z = make_float4(0.f, 0.f, 0.f, 0.f);
    if (i < NN * C1 / 4)  g_out1[i] = z;
    if (i < NN * HID / 4) g_out2[i] = z;
    if (i < NN * 4)       g_amax1[i] = ENC_NEG_INF;
    if (i < NN) { g_den1[i] = z; g_den2[i] = 0.f; g_amax2[i] = ENC_NEG_INF; }
}

__global__ void k_prep(const float* __restrict__ We1, const float* __restrict__ ae1,
                       const float* __restrict__ We2, const float* __restrict__ ae2) {
    int t = threadIdx.x;
    if (t < EDIM * HEADS) {
        int d = t >> 2, h = t & 3;
        float s = 0.f;
        for (int c = 0; c < HID; c++) s += We1[d * C1 + h * HID + c] * ae1[h * HID + c];
        g_v1[t] = s;
    }
    if (t < EDIM) {
        float s = 0.f;
        for (int c = 0; c < HID; c++) s += We2[t * HID + c] * ae2[c];
        g_v2[t] = s;
    }
}

// h1 = x @ W1  (16 nodes per 256-thread block; thread t owns output col t)
__global__ __launch_bounds__(256) void k_gemm1(const float* __restrict__ x,
                                               const float* __restrict__ W1) {
    __shared__ float xs[16][IND];
    int node0 = blockIdx.x * 16;
    int t = threadIdx.x;
    const float4* xv = (const float4*)(x + (size_t)node0 * IND);
    ((float4*)&xs[0][0])[t]       = xv[t];
    ((float4*)&xs[0][0])[t + 256] = xv[t + 256];
    __syncthreads();
    float acc[16];
#pragma unroll
    for (int i = 0; i < 16; i++) acc[i] = 0.f;
#pragma unroll 4
    for (int k = 0; k < IND; k++) {
        float w = W1[k * C1 + t];
#pragma unroll
        for (int i = 0; i < 16; i++) acc[i] = fmaf(xs[i][k], w, acc[i]);
    }
    float* h1 = (float*)g_h1;
#pragma unroll
    for (int i = 0; i < 16; i++) h1[(size_t)(node0 + i) * C1 + t] = acc[i];
}

// per-node attention dots: a_src1[n,h] = h1[n,h,:].as1[h,:]  (warp per node)
__global__ __launch_bounds__(256) void k_att1(const float* __restrict__ as1,
                                              const float* __restrict__ ad1) {
    int warp = (blockIdx.x * blockDim.x + threadIdx.x) >> 5;
    int lane = threadIdx.x & 31;
    if (warp >= NN) return;
    const float4* hrow = g_h1 + (size_t)warp * 64;
    float s = 0.f, d = 0.f;
#pragma unroll
    for (int j = 0; j < 2; j++) {
        int q = lane * 2 + j;             // channels 8*lane..8*lane+7, head = lane/8
        float4 hv = hrow[q];
        float4 av = ((const float4*)as1)[q];
        float4 dv = ((const float4*)ad1)[q];
        s += hv.x * av.x + hv.y * av.y + hv.z * av.z + hv.w * av.w;
        d += hv.x * dv.x + hv.y * dv.y + hv.z * dv.z + hv.w * dv.w;
    }
#pragma unroll
    for (int o = 4; o >= 1; o >>= 1) {
        s += __shfl_xor_sync(0xFFFFFFFFu, s, o);
        d += __shfl_xor_sync(0xFFFFFFFFu, d, o);
    }
    if ((lane & 7) == 0) {
        int h = lane >> 3;
        ((float*)g_asrc1)[warp * 4 + h] = s;
        ((float*)g_adst1)[warp * 4 + h] = d;
    }
}

// per-edge logits (both layers' a_e), store pre, atomicMax per-dst
__global__ __launch_bounds__(256) void k_edge1(const int* __restrict__ ei,
                                               const float* __restrict__ eattr) {
    __shared__ float v1s[EDIM * HEADS];
    __shared__ float v2s[EDIM];
    if (threadIdx.x < EDIM * HEADS) v1s[threadIdx.x] = g_v1[threadIdx.x];
    if (threadIdx.x < EDIM)         v2s[threadIdx.x] = g_v2[threadIdx.x];
    __syncthreads();
    int e = blockIdx.x * blockDim.x + threadIdx.x;
    if (e >= NE) return;
    int s = ei[e], d = ei[NE + e];
    const float4* ea = (const float4*)(eattr + (size_t)e * EDIM);
    float ae[4] = {0.f, 0.f, 0.f, 0.f};
    float ae2 = 0.f;
#pragma unroll
    for (int j = 0; j < 4; j++) {
        float4 v = ea[j];
        float vals[4] = {v.x, v.y, v.z, v.w};
#pragma unroll
        for (int m = 0; m < 4; m++) {
            int dd = j * 4 + m;
            float ev = vals[m];
#pragma unroll
            for (int h = 0; h < 4; h++) ae[h] = fmaf(ev, v1s[dd * 4 + h], ae[h]);
            ae2 = fmaf(ev, v2s[dd], ae2);
        }
    }
    g_ae2[e] = ae2;
    float4 av = g_asrc1[s], dv = g_adst1[d];
    float4 pre;
    pre.x = lrelu(av.x + dv.x + ae[0]);
    pre.y = lrelu(av.y + dv.y + ae[1]);
    pre.z = lrelu(av.z + dv.z + ae[2]);
    pre.w = lrelu(av.w + dv.w + ae[3]);
    g_scr1[e] = pre;
    atomicMax(&g_amax1[d * 4 + 0], f2o(pre.x));
    atomicMax(&g_amax1[d * 4 + 1], f2o(pre.y));
    atomicMax(&g_amax1[d * 4 + 2], f2o(pre.z));
    atomicMax(&g_amax1[d * 4 + 3], f2o(pre.w));
}

__global__ __launch_bounds__(256) void k_exp1(const int* __restrict__ ei) {
    int e = blockIdx.x * blockDim.x + threadIdx.x;
    if (e >= NE) return;
    int d = ei[NE + e];
    float4 pre = g_scr1[e];
    uint4 mu = ((const uint4*)g_amax1)[d];
    float4 ex;
    ex.x = __expf(pre.x - o2f(mu.x));
    ex.y = __expf(pre.y - o2f(mu.y));
    ex.z = __expf(pre.z - o2f(mu.z));
    ex.w = __expf(pre.w - o2f(mu.w));
    g_scr1[e] = ex;
    red_add_v4((float*)&g_den1[d], ex);
}

// layer-1 aggregation: out1[dst] += h1[src] * alpha   (warp per edge, 256 ch)
__global__ __launch_bounds__(256) void k_agg1(const int* __restrict__ ei) {
    int gw = (blockIdx.x * blockDim.x + threadIdx.x) >> 5;
    int lane = threadIdx.x & 31;
    if (gw >= NE) return;
    int s = ei[gw], d = ei[NE + gw];
    float4 ex = g_scr1[gw];
    float4 dn = g_den1[d];
    float al[4] = {ex.x / (dn.x + 1e-16f), ex.y / (dn.y + 1e-16f),
                   ex.z / (dn.z + 1e-16f), ex.w / (dn.w + 1e-16f)};
    const float4* hs = g_h1 + (size_t)s * 64;
    float* od = (float*)(g_out1 + (size_t)d * 64);
#pragma unroll
    for (int j = 0; j < 2; j++) {
        int q = j * 32 + lane;
        float a = al[q >> 4];
        float4 v = hs[q];
        v.x *= a; v.y *= a; v.z *= a; v.w *= a;
        red_add_v4(od + q * 4, v);
    }
}

// h2 = relu(out1 + b1) @ W2, plus layer-2 attention dots (4 nodes / block)
__global__ __launch_bounds__(256) void k_gemm2(const float* __restrict__ W2,
                                               const float* __restrict__ b1,
                                               const float* __restrict__ as2,
                                               const float* __restrict__ ad2) {
    __shared__ float xs[4][C1];
    __shared__ float rs[256], rd[256];
    int node0 = blockIdx.x * 4;
    int t = threadIdx.x;
    {
        float4 v = (g_out1 + (size_t)node0 * 64)[t];
        float4 b = ((const float4*)b1)[t & 63];
        v.x = fmaxf(v.x + b.x, 0.f);
        v.y = fmaxf(v.y + b.y, 0.f);
        v.z = fmaxf(v.z + b.z, 0.f);
        v.w = fmaxf(v.w + b.w, 0.f);
        ((float4*)xs)[t] = v;
    }
    __syncthreads();
    int ni = t >> 6, c = t & 63;
    float acc = 0.f;
#pragma unroll 4
    for (int k = 0; k < C1; k++) acc = fmaf(xs[ni][k], W2[k * HID + c], acc);
    ((float*)g_h2)[(size_t)(node0 + ni) * HID + c] = acc;
    rs[t] = acc * as2[c];
    rd[t] = acc * ad2[c];
    __syncthreads();
    int w = t >> 5, lane = t & 31;
    if (w < 4) {
        float v = rs[w * 64 + lane] + rs[w * 64 + 32 + lane];
#pragma unroll
        for (int o = 16; o >= 1; o >>= 1) v += __shfl_xor_sync(0xFFFFFFFFu, v, o);
        if (lane == 0) g_asrc2[node0 + w] = v;
    } else {
        int w2 = w - 4;
        float v = rd[w2 * 64 + lane] + rd[w2 * 64 + 32 + lane];
#pragma unroll
        for (int o = 16; o >= 1; o >>= 1) v += __shfl_xor_sync(0xFFFFFFFFu, v, o);
        if (lane == 0) g_adst2[node0 + w2] = v;
    }
}

__global__ __launch_bounds__(256) void k_edge2(const int* __restrict__ ei) {
    int e = blockIdx.x * blockDim.x + threadIdx.x;
    if (e >= NE) return;
    int s = ei[e], d = ei[NE + e];
    float pre = lrelu(g_asrc2[s] + g_adst2[d] + g_ae2[e]);
    g_scr2[e] = pre;
    atomicMax(&g_amax2[d], f2o(pre));
}

__global__ __launch_bounds__(256) void k_exp2(const int* __restrict__ ei) {
    int e = blockIdx.x * blockDim.x + threadIdx.x;
    if (e >= NE) return;
    int d = ei[NE + e];
    float ex = __expf(g_scr2[e] - o2f(g_amax2[d]));
    g_scr2[e] = ex;
    atomicAdd(&g_den2[d], ex);
}

// layer-2 aggregation: 16 threads per edge, 64 channels
__global__ __launch_bounds__(256) void k_agg2(const int* __restrict__ ei) {
    int gid = blockIdx.x * blockDim.x + threadIdx.x;
    int e = gid >> 4, l = gid & 15;
    if (e >= NE) return;
    int s = ei[e], d = ei[NE + e];
    float a = g_scr2[e] / (g_den2[d] + 1e-16f);
    float4 v = g_h2[(size_t)s * 16 + l];
    v.x *= a; v.y *= a; v.z *= a; v.w *= a;
    red_add_v4((float*)g_out2 + (size_t)d * 64 + l * 4, v);
}

// out = relu(out2 + b2) @ Wlin + blin  (warp per node)
__global__ __launch_bounds__(256) void k_final(const float* __restrict__ b2,
                                               const float* __restrict__ Wlin,
                                               const float* __restrict__ blin,
                                               float* __restrict__ out) {
    int n = (blockIdx.x * blockDim.x + threadIdx.x) >> 5;
    int lane = threadIdx.x & 31;
    if (n >= NN) return;
    const float* row = (const float*)g_out2 + (size_t)n * 64;
    float acc = 0.f;
#pragma unroll
    for (int j = 0; j < 2; j++) {
        int c = lane + j * 32;
        float v = fmaxf(row[c] + b2[c], 0.f);
        acc = fmaf(v, Wlin[c], acc);
    }
#pragma unroll
    for (int o = 16; o >= 1; o >>= 1) acc += __shfl_xor_sync(0xFFFFFFFFu, acc, o);
    if (lane == 0) out[n] = acc + blin[0];
}

// ---------------- launch ----------------
extern "C" void kernel_launch(void* const* d_in, const int* in_sizes, int n_in,
                              void* d_out, int out_size) {
    const float* x     = (const float*)d_in[0];
    const int*   ei    = (const int*)d_in[1];
    const float* eattr = (const float*)d_in[2];
    const float* W1    = (const float*)d_in[3];
    const float* We1   = (const float*)d_in[4];
    const float* as1   = (const float*)d_in[5];
    const float* ad1   = (const float*)d_in[6];
    const float* ae1   = (const float*)d_in[7];
    const float* b1    = (const float*)d_in[8];
    const float* W2    = (const float*)d_in[9];
    const float* We2   = (const float*)d_in[10];
    const float* as2   = (const float*)d_in[11];
    const float* ad2   = (const float*)d_in[12];
    const float* ae2   = (const float*)d_in[13];
    const float* b2    = (const float*)d_in[14];
    const float* Wlin  = (const float*)d_in[15];
    const float* blin  = (const float*)d_in[16];
    float* out = (float*)d_out;

    k_init<<<(NN * C1 / 4 + 255) / 256, 256>>>();
    k_prep<<<1, 64>>>(We1, ae1, We2, ae2);
    k_gemm1<<<NN / 16, 256>>>(x, W1);
    k_att1<<<(NN * 32 + 255) / 256, 256>>>(as1, ad1);
    k_edge1<<<NE / 256, 256>>>(ei, eattr);
    k_exp1<<<NE / 256, 256>>>(ei);
    k_agg1<<<NE * 32 / 256, 256>>>(ei);
    k_gemm2<<<NN / 4, 256>>>(W2, b1, as2, ad2);
    k_edge2<<<NE / 256, 256>>>(ei);
    k_exp2<<<NE / 256, 256>>>(ei);
    k_agg2<<<NE * 16 / 256, 256>>>(ei);
    k_final<<<(NN * 32 + 255) / 256, 256>>>(b2, Wlin, blin, out);
}

// round 3
// speedup vs baseline: 1.3757x; 1.3757x over previous
#include <cuda_runtime.h>

#define NN 50000
#define NE 800000
#define IND 128
#define HID 64
#define HEADS 4
#define C1 256            // HEADS*HID
#define EDIM 16
#define NBLK_SCAN 196     // ceil(50000/256)

// ---------------- scratch (device globals) ----------------
__device__ float4   g_h1[NN * C1 / 4];      // [N,256] layer-1 feats
__device__ float4   g_out1[NN * C1 / 4];    // layer-1 aggregate
__device__ float4   g_h2[NN * HID / 4];     // [N,64]  layer-2 feats
__device__ float4   g_out2[NN * HID / 4];   // layer-2 aggregate
__device__ float4   g_scr1[NE];             // per-edge exp(logit), 4 heads
__device__ float    g_scr2[NE];             // per-edge exp(logit), 1 head
__device__ float    g_ae2[NE];              // layer-2 edge-attr term
__device__ float4   g_asrc1[NN], g_adst1[NN];
__device__ float    g_asrc2[NN], g_adst2[NN];
__device__ float    g_v1[EDIM * HEADS];     // (We1 . ae1) collapsed
__device__ float    g_v2[EDIM];
// CSR
__device__ unsigned g_deg[NN];
__device__ unsigned g_cnt[NN];
__device__ unsigned g_ptr[NN + 1];
__device__ unsigned g_bsum[256];
__device__ int2     g_csr[NE];              // (edge_id, src)

// ---------------- helpers ----------------
__device__ __forceinline__ float lrelu(float x) { return x > 0.f ? x : 0.2f * x; }

__device__ __forceinline__ void fma2(unsigned long long& d,
                                     unsigned long long a, unsigned long long b) {
    asm("fma.rn.f32x2 %0, %1, %2, %0;" : "+l"(d) : "l"(a), "l"(b));
}
__device__ __forceinline__ unsigned long long pack2(float v) {
    unsigned long long r;
    asm("mov.b64 %0, {%1,%1};" : "=l"(r) : "r"(__float_as_uint(v)));
    return r;
}
__device__ __forceinline__ float lo32(unsigned long long v) {
    return __uint_as_float((unsigned)v);
}
__device__ __forceinline__ float hi32(unsigned long long v) {
    return __uint_as_float((unsigned)(v >> 32));
}

// ---------------- kernels ----------------
__global__ __launch_bounds__(256) void k_init() {
    int i = blockIdx.x * blockDim.x + threadIdx.x;
    if (i < NN) { g_deg[i] = 0u; g_cnt[i] = 0u; }
}

__global__ void k_prep(const float* __restrict__ We1, const float* __restrict__ ae1,
                       const float* __restrict__ We2, const float* __restrict__ ae2) {
    int t = threadIdx.x;
    if (t < EDIM * HEADS) {
        int d = t >> 2, h = t & 3;
        float s = 0.f;
        for (int c = 0; c < HID; c++) s += We1[d * C1 + h * HID + c] * ae1[h * HID + c];
        g_v1[t] = s;
    }
    if (t < EDIM) {
        float s = 0.f;
        for (int c = 0; c < HID; c++) s += We2[t * HID + c] * ae2[c];
        g_v2[t] = s;
    }
}

// ---- CSR build ----
__global__ __launch_bounds__(256) void k_hist(const int* __restrict__ ei) {
    int e = blockIdx.x * blockDim.x + threadIdx.x;
    if (e < NE) atomicAdd(&g_deg[ei[NE + e]], 1u);
}

__global__ __launch_bounds__(256) void k_scan1() {
    __shared__ unsigned wsum[8];
    int t = threadIdx.x;
    int i = blockIdx.x * 256 + t;
    unsigned v = (i < NN) ? g_deg[i] : 0u;
    unsigned lane = t & 31, wid = t >> 5;
    unsigned incl = v;
#pragma unroll
    for (int o = 1; o < 32; o <<= 1) {
        unsigned u = __shfl_up_sync(0xFFFFFFFFu, incl, o);
        if (lane >= o) incl += u;
    }
    if (lane == 31) wsum[wid] = incl;
    __syncthreads();
    if (t < 8) {
        unsigned w = wsum[t];
        unsigned inc = w;
#pragma unroll
        for (int o = 1; o < 8; o <<= 1) {
            unsigned u = __shfl_up_sync(0xFFu, inc, o);
            if (t >= (unsigned)o) inc += u;
        }
        wsum[t] = inc - w;                      // exclusive warp offset
        if (t == 7) g_bsum[blockIdx.x] = inc;   // block total
    }
    __syncthreads();
    if (i < NN) g_ptr[i] = incl - v + wsum[wid];
}

__global__ void k_scan2() {
    __shared__ unsigned wsum[8];
    int t = threadIdx.x;
    unsigned v = (t < NBLK_SCAN) ? g_bsum[t] : 0u;
    unsigned lane = t & 31, wid = t >> 5;
    unsigned incl = v;
#pragma unroll
    for (int o = 1; o < 32; o <<= 1) {
        unsigned u = __shfl_up_sync(0xFFFFFFFFu, incl, o);
        if (lane >= o) incl += u;
    }
    if (lane == 31) wsum[wid] = incl;
    __syncthreads();
    if (t < 8) {
        unsigned w = wsum[t];
        unsigned inc = w;
#pragma unroll
        for (int o = 1; o < 8; o <<= 1) {
            unsigned u = __shfl_up_sync(0xFFu, inc, o);
            if (t >= (unsigned)o) inc += u;
        }
        wsum[t] = inc - w;
    }
    __syncthreads();
    if (t < NBLK_SCAN) g_bsum[t] = incl - v + wsum[wid];
}

__global__ __launch_bounds__(256) void k_scan3() {
    int i = blockIdx.x * blockDim.x + threadIdx.x;
    if (i < NN) g_ptr[i] += g_bsum[i >> 8];
    if (i == NN) g_ptr[NN] = NE;
}

__global__ __launch_bounds__(256) void k_scatter(const int* __restrict__ ei) {
    int e = blockIdx.x * blockDim.x + threadIdx.x;
    if (e >= NE) return;
    int s = ei[e], d = ei[NE + e];
    unsigned pos = g_ptr[d] + atomicAdd(&g_cnt[d], 1u);
    g_csr[pos] = make_int2(e, s);
}

// ---- h1 = x @ W1 : 16 nodes/block, packed f32x2 over node pairs ----
__global__ __launch_bounds__(256) void k_gemm1(const float* __restrict__ x,
                                               const float* __restrict__ W1) {
    __shared__ float2 xs[IND][8];               // [k][node_pair]
    int node0 = blockIdx.x * 16;
    int t = threadIdx.x;
#pragma unroll
    for (int i = 0; i < 8; i++) {
        int j = i * 256 + t;                    // 0..2047
        int n = j >> 7, k = j & 127;
        float v = x[(size_t)(node0 + n) * IND + k];
        ((float*)&xs[k][n >> 1])[n & 1] = v;
    }
    __syncthreads();
    unsigned long long acc[8];
#pragma unroll
    for (int i = 0; i < 8; i++) acc[i] = 0ull;
#pragma unroll 4
    for (int k = 0; k < IND; k++) {
        unsigned long long w2 = pack2(W1[k * C1 + t]);
#pragma unroll
        for (int i = 0; i < 8; i++) {
            unsigned long long xv = *reinterpret_cast<const unsigned long long*>(&xs[k][i]);
            fma2(acc[i], xv, w2);
        }
    }
    float* h1 = (float*)g_h1;
#pragma unroll
    for (int i = 0; i < 8; i++) {
        h1[(size_t)(node0 + 2 * i) * C1 + t]     = lo32(acc[i]);
        h1[(size_t)(node0 + 2 * i + 1) * C1 + t] = hi32(acc[i]);
    }
}

// per-node attention dots (warp per node)
__global__ __launch_bounds__(256) void k_att1(const float* __restrict__ as1,
                                              const float* __restrict__ ad1) {
    int warp = (blockIdx.x * blockDim.x + threadIdx.x) >> 5;
    int lane = threadIdx.x & 31;
    if (warp >= NN) return;
    const float4* hrow = g_h1 + (size_t)warp * 64;
    float s = 0.f, d = 0.f;
#pragma unroll
    for (int j = 0; j < 2; j++) {
        int q = lane * 2 + j;
        float4 hv = hrow[q];
        float4 av = ((const float4*)as1)[q];
        float4 dv = ((const float4*)ad1)[q];
        s += hv.x * av.x + hv.y * av.y + hv.z * av.z + hv.w * av.w;
        d += hv.x * dv.x + hv.y * dv.y + hv.z * dv.z + hv.w * dv.w;
    }
#pragma unroll
    for (int o = 4; o >= 1; o >>= 1) {
        s += __shfl_xor_sync(0xFFFFFFFFu, s, o);
        d += __shfl_xor_sync(0xFFFFFFFFu, d, o);
    }
    if ((lane & 7) == 0) {
        int h = lane >> 3;
        ((float*)g_asrc1)[warp * 4 + h] = s;
        ((float*)g_adst1)[warp * 4 + h] = d;
    }
}

// per-edge: layer-1 exp(logit) for 4 heads + layer-2 edge term (no max pass)
__global__ __launch_bounds__(256) void k_edge1(const int* __restrict__ ei,
                                               const float* __restrict__ eattr) {
    __shared__ float v1s[EDIM * HEADS];
    __shared__ float v2s[EDIM];
    if (threadIdx.x < EDIM * HEADS) v1s[threadIdx.x] = g_v1[threadIdx.x];
    if (threadIdx.x < EDIM)         v2s[threadIdx.x] = g_v2[threadIdx.x];
    __syncthreads();
    int e = blockIdx.x * blockDim.x + threadIdx.x;
    if (e >= NE) return;
    int s = ei[e], d = ei[NE + e];
    const float4* ea = (const float4*)(eattr + (size_t)e * EDIM);
    float ae[4] = {0.f, 0.f, 0.f, 0.f};
    float aev2 = 0.f;
#pragma unroll
    for (int j = 0; j < 4; j++) {
        float4 v = ea[j];
        float vals[4] = {v.x, v.y, v.z, v.w};
#pragma unroll
        for (int m = 0; m < 4; m++) {
            int dd = j * 4 + m;
            float ev = vals[m];
#pragma unroll
            for (int h = 0; h < 4; h++) ae[h] = fmaf(ev, v1s[dd * 4 + h], ae[h]);
            aev2 = fmaf(ev, v2s[dd], aev2);
        }
    }
    g_ae2[e] = aev2;
    float4 av = g_asrc1[s], dv = g_adst1[d];
    float4 ex;
    ex.x = __expf(lrelu(av.x + dv.x + ae[0]));
    ex.y = __expf(lrelu(av.y + dv.y + ae[1]));
    ex.z = __expf(lrelu(av.z + dv.z + ae[2]));
    ex.w = __expf(lrelu(av.w + dv.w + ae[3]));
    g_scr1[e] = ex;
}

// layer-1 aggregation: warp per dst node, gather + register accumulate
__global__ __launch_bounds__(256) void k_agg1() {
    int w = (blockIdx.x * blockDim.x + threadIdx.x) >> 5;
    int lane = threadIdx.x & 31;
    if (w >= NN) return;
    unsigned beg = g_ptr[w], end = g_ptr[w + 1];
    // denominator
    float4 ds = make_float4(0.f, 0.f, 0.f, 0.f);
    for (unsigned j = beg + lane; j < end; j += 32) {
        float4 ex = g_scr1[g_csr[j].x];
        ds.x += ex.x; ds.y += ex.y; ds.z += ex.z; ds.w += ex.w;
    }
#pragma unroll
    for (int o = 16; o >= 1; o >>= 1) {
        ds.x += __shfl_xor_sync(0xFFFFFFFFu, ds.x, o);
        ds.y += __shfl_xor_sync(0xFFFFFFFFu, ds.y, o);
        ds.z += __shfl_xor_sync(0xFFFFFFFFu, ds.z, o);
        ds.w += __shfl_xor_sync(0xFFFFFFFFu, ds.w, o);
    }
    float4 inv;
    inv.x = 1.f / (ds.x + 1e-16f); inv.y = 1.f / (ds.y + 1e-16f);
    inv.z = 1.f / (ds.z + 1e-16f); inv.w = 1.f / (ds.w + 1e-16f);
    float4 a0 = make_float4(0.f, 0.f, 0.f, 0.f);
    float4 a1 = make_float4(0.f, 0.f, 0.f, 0.f);
    int q0 = lane, q1 = lane + 32;
    int h0 = q0 >> 4, h1i = q1 >> 4;
    for (unsigned j = beg; j < end; j++) {
        int2 es = g_csr[j];
        float4 ex = g_scr1[es.x];
        float al0 = ((float*)&ex)[h0] * ((float*)&inv)[h0];
        float al1 = ((float*)&ex)[h1i] * ((float*)&inv)[h1i];
        const float4* hrow = g_h1 + (size_t)es.y * 64;
        float4 v0 = hrow[q0];
        float4 v1 = hrow[q1];
        a0.x = fmaf(v0.x, al0, a0.x); a0.y = fmaf(v0.y, al0, a0.y);
        a0.z = fmaf(v0.z, al0, a0.z); a0.w = fmaf(v0.w, al0, a0.w);
        a1.x = fmaf(v1.x, al1, a1.x); a1.y = fmaf(v1.y, al1, a1.y);
        a1.z = fmaf(v1.z, al1, a1.z); a1.w = fmaf(v1.w, al1, a1.w);
    }
    float4* od = g_out1 + (size_t)w * 64;
    od[q0] = a0;
    od[q1] = a1;
}

// h2 = relu(out1+b1) @ W2 + layer-2 attention dots. 8 nodes/block, f32x2.
__global__ __launch_bounds__(256) void k_gemm2(const float* __restrict__ W2,
                                               const float* __restrict__ b1,
                                               const float* __restrict__ as2,
                                               const float* __restrict__ ad2) {
    __shared__ float xs[8][C1];                 // 8 KB
    int node0 = blockIdx.x * 8;
    int t = threadIdx.x;
#pragma unroll
    for (int i = 0; i < 2; i++) {
        int j = i * 256 + t;                    // float4 index, 0..511
        int n = j >> 6, q = j & 63;
        float4 v = g_out1[(size_t)(node0 + n) * 64 + q];
        float4 b = ((const float4*)b1)[q];
        v.x = fmaxf(v.x + b.x, 0.f); v.y = fmaxf(v.y + b.y, 0.f);
        v.z = fmaxf(v.z + b.z, 0.f); v.w = fmaxf(v.w + b.w, 0.f);
        ((float4*)&xs[n][0])[q] = v;
    }
    __syncthreads();
    int ni = t >> 5, c = t & 31;                // node-in-block, col pair
    unsigned long long acc = 0ull;
#pragma unroll 4
    for (int k = 0; k < C1; k++) {
        unsigned long long xv = pack2(xs[ni][k]);
        unsigned long long wv = *reinterpret_cast<const unsigned long long*>(&W2[k * HID + 2 * c]);
        fma2(acc, xv, wv);
    }
    float vlo = lo32(acc), vhi = hi32(acc);
    float* h2 = (float*)g_h2;
    h2[(size_t)(node0 + ni) * HID + 2 * c]     = vlo;
    h2[(size_t)(node0 + ni) * HID + 2 * c + 1] = vhi;
    float rs = vlo * as2[2 * c] + vhi * as2[2 * c + 1];
    float rd = vlo * ad2[2 * c] + vhi * ad2[2 * c + 1];
#pragma unroll
    for (int o = 16; o >= 1; o >>= 1) {
        rs += __shfl_xor_sync(0xFFFFFFFFu, rs, o);
        rd += __shfl_xor_sync(0xFFFFFFFFu, rd, o);
    }
    if (c == 0) {
        g_asrc2[node0 + ni] = rs;
        g_adst2[node0 + ni] = rd;
    }
}

__global__ __launch_bounds__(256) void k_edge2(const int* __restrict__ ei) {
    int e = blockIdx.x * blockDim.x + threadIdx.x;
    if (e >= NE) return;
    int s = ei[e], d = ei[NE + e];
    g_scr2[e] = __expf(lrelu(g_asrc2[s] + g_adst2[d] + g_ae2[e]));
}

// layer-2 aggregation: warp per dst node, 2 channels per lane
__global__ __launch_bounds__(256) void k_agg2() {
    int w = (blockIdx.x * blockDim.x + threadIdx.x) >> 5;
    int lane = threadIdx.x & 31;
    if (w >= NN) return;
    unsigned beg = g_ptr[w], end = g_ptr[w + 1];
    float ds = 0.f;
    for (unsigned j = beg + lane; j < end; j += 32) ds += g_scr2[g_csr[j].x];
#pragma unroll
    for (int o = 16; o >= 1; o >>= 1) ds += __shfl_xor_sync(0xFFFFFFFFu, ds, o);
    float inv = 1.f / (ds + 1e-16f);
    float2 acc = make_float2(0.f, 0.f);
    const float2* h2 = (const float2*)g_h2;
    for (unsigned j = beg; j < end; j++) {
        int2 es = g_csr[j];
        float al = g_scr2[es.x] * inv;
        float2 v = h2[(size_t)es.y * 32 + lane];
        acc.x = fmaf(v.x, al, acc.x);
        acc.y = fmaf(v.y, al, acc.y);
    }
    ((float2*)g_out2)[(size_t)w * 32 + lane] = acc;
}

// out = relu(out2 + b2) @ Wlin + blin  (warp per node)
__global__ __launch_bounds__(256) void k_final(const float* __restrict__ b2,
                                               const float* __restrict__ Wlin,
                                               const float* __restrict__ blin,
                                               float* __restrict__ out) {
    int n = (blockIdx.x * blockDim.x + threadIdx.x) >> 5;
    int lane = threadIdx.x & 31;
    if (n >= NN) return;
    const float* row = (const float*)g_out2 + (size_t)n * 64;
    float acc = 0.f;
#pragma unroll
    for (int j = 0; j < 2; j++) {
        int c = lane + j * 32;
        float v = fmaxf(row[c] + b2[c], 0.f);
        acc = fmaf(v, Wlin[c], acc);
    }
#pragma unroll
    for (int o = 16; o >= 1; o >>= 1) acc += __shfl_xor_sync(0xFFFFFFFFu, acc, o);
    if (lane == 0) out[n] = acc + blin[0];
}

// ---------------- launch ----------------
extern "C" void kernel_launch(void* const* d_in, const int* in_sizes, int n_in,
                              void* d_out, int out_size) {
    const float* x     = (const float*)d_in[0];
    const int*   ei    = (const int*)d_in[1];
    const float* eattr = (const float*)d_in[2];
    const float* W1    = (const float*)d_in[3];
    const float* We1   = (const float*)d_in[4];
    const float* as1   = (const float*)d_in[5];
    const float* ad1   = (const float*)d_in[6];
    const float* ae1   = (const float*)d_in[7];
    const float* b1    = (const float*)d_in[8];
    const float* W2    = (const float*)d_in[9];
    const float* We2   = (const float*)d_in[10];
    const float* as2   = (const float*)d_in[11];
    const float* ad2   = (const float*)d_in[12];
    const float* ae2   = (const float*)d_in[13];
    const float* b2    = (const float*)d_in[14];
    const float* Wlin  = (const float*)d_in[15];
    const float* blin  = (const float*)d_in[16];
    float* out = (float*)d_out;

    k_init<<<(NN + 255) / 256, 256>>>();
    k_prep<<<1, 64>>>(We1, ae1, We2, ae2);
    k_hist<<<NE / 256, 256>>>(ei);
    k_scan1<<<NBLK_SCAN, 256>>>();
    k_scan2<<<1, 256>>>();
    k_scan3<<<(NN + 256) / 256, 256>>>();
    k_scatter<<<NE / 256, 256>>>(ei);
    k_gemm1<<<NN / 16, 256>>>(x, W1);
    k_att1<<<(NN * 32 + 255) / 256, 256>>>(as1, ad1);
    k_edge1<<<NE / 256, 256>>>(ei, eattr);
    k_agg1<<<(NN * 32 + 255) / 256, 256>>>();
    k_gemm2<<<NN / 8, 256>>>(W2, b1, as2, ad2);
    k_edge2<<<NE / 256, 256>>>(ei);
    k_agg2<<<(NN * 32 + 255) / 256, 256>>>();
    k_final<<<(NN * 32 + 255) / 256, 256>>>(b2, Wlin, blin, out);
}